// round 5
// baseline (speedup 1.0000x reference)
#include <cuda_runtime.h>
#include <math.h>

#define D 128
#define NMAX 50000
#define EMAX 800000
#define BM 64

// Scratch (device globals — no allocation allowed)
__device__ float g_xw[(size_t)NMAX * D];   // x @ W
__device__ float g_p1[NMAX];               // x . w_pred[:128]
__device__ float g_p2[NMAX];               // x . w_pred[128:]
__device__ float g_deg[NMAX];              // weighted in-degree (init 1 self loop)
__device__ float g_dis[NMAX];              // deg^{-1/2}
__device__ float g_ew[EMAX];               // sigmoid edge weights
__device__ int   g_cnt[NMAX];              // integer in-degree (edges only)
__device__ int   g_rowstart[NMAX + 1];     // CSR row offsets (by target)
__device__ int   g_cursor[NMAX];           // fill cursors
__device__ int   g_eidx[EMAX];             // edge ids bucketed by target

// ---------------------------------------------------------------------------
// K1: per-node dot products with the two halves of w_pred; init deg/cnt.
// ---------------------------------------------------------------------------
__global__ void k_precompute(const float* __restrict__ x,
                             const float* __restrict__ wp, int n) {
    int warp = (blockIdx.x * blockDim.x + threadIdx.x) >> 5;
    int lane = threadIdx.x & 31;
    if (warp >= n) return;
    float4 xv = ((const float4*)(x + (size_t)warp * D))[lane];
    float4 w1 = ((const float4*)wp)[lane];
    float4 w2 = ((const float4*)(wp + D))[lane];
    float s1 = xv.x * w1.x + xv.y * w1.y + xv.z * w1.z + xv.w * w1.w;
    float s2 = xv.x * w2.x + xv.y * w2.y + xv.z * w2.z + xv.w * w2.w;
#pragma unroll
    for (int o = 16; o > 0; o >>= 1) {
        s1 += __shfl_xor_sync(0xffffffffu, s1, o);
        s2 += __shfl_xor_sync(0xffffffffu, s2, o);
    }
    if (lane == 0) {
        g_p1[warp] = s1;
        g_p2[warp] = s2;
        g_deg[warp] = 1.0f;
        g_cnt[warp] = 0;
    }
}

// ---------------------------------------------------------------------------
// K2: edge weights (sigmoid) + weighted degree + integer counts.
// ---------------------------------------------------------------------------
__global__ void k_edge(const int* __restrict__ src, const int* __restrict__ tgt,
                       const float* __restrict__ bp, int e) {
    int i = blockIdx.x * blockDim.x + threadIdx.x;
    if (i >= e) return;
    int s = src[i], t = tgt[i];
    float z = g_p1[s] + g_p2[t] + bp[0];
    float w = __fdividef(1.0f, 1.0f + __expf(-z));
    g_ew[i] = w;
    atomicAdd(&g_deg[t], w);
    atomicAdd(&g_cnt[t], 1);
}

// ---------------------------------------------------------------------------
// K3: single-block scan of counts -> rowstart/cursor; dis = rsqrt(deg).
// ---------------------------------------------------------------------------
__global__ void k_scan(int n) {
    __shared__ int ssum[1024];
    int tid = threadIdx.x;
    int chunk = (n + 1023) >> 10;
    int lo = tid * chunk;
    int hi = min(n, lo + chunk);
    int s = 0;
    for (int j = lo; j < hi; j++) s += g_cnt[j];
    ssum[tid] = s;
    __syncthreads();
    for (int off = 1; off < 1024; off <<= 1) {
        int v = (tid >= off) ? ssum[tid - off] : 0;
        __syncthreads();
        ssum[tid] += v;
        __syncthreads();
    }
    int run = ssum[tid] - s;  // exclusive prefix
    for (int j = lo; j < hi; j++) {
        g_rowstart[j] = run;
        g_cursor[j] = run;
        run += g_cnt[j];
        float dg = g_deg[j];
        g_dis[j] = (dg > 0.f) ? rsqrtf(dg) : 0.f;
    }
    if (tid == 0) g_rowstart[n] = ssum[1023];
}

// ---------------------------------------------------------------------------
// K4: bucket edge ids by target (CSR fill).
// ---------------------------------------------------------------------------
__global__ void k_fill(const int* __restrict__ tgt, int e) {
    int i = blockIdx.x * blockDim.x + threadIdx.x;
    if (i >= e) return;
    int pos = atomicAdd(&g_cursor[tgt[i]], 1);
    g_eidx[pos] = i;
}

// ---------------------------------------------------------------------------
// K5: xw = x @ W with packed FFMA2 (proven R4 kernel, unchanged).
// ---------------------------------------------------------------------------
__global__ void k_gemm(const float* __restrict__ x, const float* __restrict__ W,
                       int n) {
    extern __shared__ float sh[];
    float* Ws = sh;            // [k][j]  128*128
    float* Xs = sh + D * D;    // [r][k]  BM*128
    int tid = threadIdx.x;
    int row0 = blockIdx.x * BM;

    for (int i = tid; i < D * D / 4; i += 256)
        ((float4*)Ws)[i] = ((const float4*)W)[i];
    for (int i = tid; i < BM * D / 4; i += 256) {
        int r = i >> 5;
        int gr = row0 + r;
        float4 v = make_float4(0.f, 0.f, 0.f, 0.f);
        if (gr < n) v = ((const float4*)x)[(size_t)gr * 32 + (i & 31)];
        ((float4*)Xs)[i] = v;
    }
    __syncthreads();

    int tcol = tid & 31;
    int trow = tid >> 5;

    unsigned long long acc[8][2];
#pragma unroll
    for (int i = 0; i < 8; i++) {
        acc[i][0] = 0ull;
        acc[i][1] = 0ull;
    }

#pragma unroll 4
    for (int k = 0; k < D; k++) {
        float4 bv = *((const float4*)&Ws[k * D + tcol * 4]);
        unsigned long long b01, b23;
        asm("mov.b64 %0, {%1, %2};" : "=l"(b01) : "f"(bv.x), "f"(bv.y));
        asm("mov.b64 %0, {%1, %2};" : "=l"(b23) : "f"(bv.z), "f"(bv.w));
#pragma unroll
        for (int i = 0; i < 8; i++) {
            float a = Xs[(trow * 8 + i) * D + k];
            unsigned long long aa;
            asm("mov.b64 %0, {%1, %1};" : "=l"(aa) : "f"(a));
            asm("fma.rn.f32x2 %0, %1, %2, %0;" : "+l"(acc[i][0])
                : "l"(aa), "l"(b01));
            asm("fma.rn.f32x2 %0, %1, %2, %0;" : "+l"(acc[i][1])
                : "l"(aa), "l"(b23));
        }
    }

#pragma unroll
    for (int i = 0; i < 8; i++) {
        int gr = row0 + trow * 8 + i;
        if (gr < n) {
            float c0, c1, c2, c3;
            asm("mov.b64 {%0, %1}, %2;" : "=f"(c0), "=f"(c1) : "l"(acc[i][0]));
            asm("mov.b64 {%0, %1}, %2;" : "=f"(c2), "=f"(c3) : "l"(acc[i][1]));
            *((float4*)&g_xw[(size_t)gr * D + tcol * 4]) =
                make_float4(c0, c1, c2, c3);
        }
    }
}

// ---------------------------------------------------------------------------
// K6: atomic-free aggregation, warp per target node.
// Edge metadata (eidx, src, coeff) is loaded ONE EDGE PER LANE (parallel,
// up to 32 edges in flight), then shuffle-broadcast; the xw row gathers in
// the inner loop have no loop-carried dependence -> high MLP on L2 hits.
// Self term + bias folded in; output row written exactly once.
// ---------------------------------------------------------------------------
__global__ void k_aggregate(const int* __restrict__ src,
                            const float* __restrict__ b,
                            float* __restrict__ out, int n) {
    int t = (blockIdx.x * blockDim.x + threadIdx.x) >> 5;
    int lane = threadIdx.x & 31;
    if (t >= n) return;
    float dt = g_dis[t];
    float4 xv = ((const float4*)g_xw)[(size_t)t * 32 + lane];
    float sc = dt * dt;
    float4 acc = make_float4(sc * xv.x, sc * xv.y, sc * xv.z, sc * xv.w);

    int p0 = g_rowstart[t];
    int cnt = g_rowstart[t + 1] - p0;

    for (int base = 0; base < cnt; base += 32) {
        int idx = base + lane;
        int s = 0;
        float c = 0.f;
        if (idx < cnt) {
            int eid = g_eidx[p0 + idx];
            s = src[eid];
            c = g_dis[s] * g_ew[eid] * dt;
        }
        int m = min(32, cnt - base);
        int j = 0;
        // unrolled by 4: four independent gathers in flight
        for (; j + 4 <= m; j += 4) {
            int s0 = __shfl_sync(0xffffffffu, s, j);
            int s1 = __shfl_sync(0xffffffffu, s, j + 1);
            int s2 = __shfl_sync(0xffffffffu, s, j + 2);
            int s3 = __shfl_sync(0xffffffffu, s, j + 3);
            float c0 = __shfl_sync(0xffffffffu, c, j);
            float c1 = __shfl_sync(0xffffffffu, c, j + 1);
            float c2 = __shfl_sync(0xffffffffu, c, j + 2);
            float c3 = __shfl_sync(0xffffffffu, c, j + 3);
            float4 v0 = ((const float4*)g_xw)[(size_t)s0 * 32 + lane];
            float4 v1 = ((const float4*)g_xw)[(size_t)s1 * 32 + lane];
            float4 v2 = ((const float4*)g_xw)[(size_t)s2 * 32 + lane];
            float4 v3 = ((const float4*)g_xw)[(size_t)s3 * 32 + lane];
            acc.x += c0 * v0.x + c1 * v1.x + c2 * v2.x + c3 * v3.x;
            acc.y += c0 * v0.y + c1 * v1.y + c2 * v2.y + c3 * v3.y;
            acc.z += c0 * v0.z + c1 * v1.z + c2 * v2.z + c3 * v3.z;
            acc.w += c0 * v0.w + c1 * v1.w + c2 * v2.w + c3 * v3.w;
        }
        for (; j < m; j++) {
            int sj = __shfl_sync(0xffffffffu, s, j);
            float cj = __shfl_sync(0xffffffffu, c, j);
            float4 v = ((const float4*)g_xw)[(size_t)sj * 32 + lane];
            acc.x += cj * v.x;
            acc.y += cj * v.y;
            acc.z += cj * v.z;
            acc.w += cj * v.w;
        }
    }

    float4 bv = ((const float4*)b)[lane];
    ((float4*)out)[(size_t)t * 32 + lane] =
        make_float4(acc.x + bv.x, acc.y + bv.y, acc.z + bv.z, acc.w + bv.w);
}

// ---------------------------------------------------------------------------
extern "C" void kernel_launch(void* const* d_in, const int* in_sizes, int n_in,
                              void* d_out, int out_size) {
    const float* x  = (const float*)d_in[0];
    const int*   ei = (const int*)d_in[1];
    const float* W  = (const float*)d_in[2];
    const float* b  = (const float*)d_in[3];
    const float* wp = (const float*)d_in[4];
    const float* bp = (const float*)d_in[5];
    float* out = (float*)d_out;

    int n = in_sizes[0] / D;
    int e = in_sizes[1] / 2;
    const int* src = ei;
    const int* tgt = ei + e;

    int smem = (D * D + BM * D) * (int)sizeof(float);  // 96 KB
    cudaFuncSetAttribute(k_gemm, cudaFuncAttributeMaxDynamicSharedMemorySize, smem);

    k_precompute<<<(n + 7) / 8, 256>>>(x, wp, n);
    k_edge<<<(e + 255) / 256, 256>>>(src, tgt, bp, e);
    k_scan<<<1, 1024>>>(n);
    k_fill<<<(e + 255) / 256, 256>>>(tgt, e);
    k_gemm<<<(n + BM - 1) / BM, 256, smem>>>(x, W, n);
    k_aggregate<<<(n * 32 + 255) / 256, 256>>>(src, b, out, n);
}

// round 6
// speedup vs baseline: 1.4733x; 1.4733x over previous
#include <cuda_runtime.h>
#include <math.h>

#define D 128
#define NMAX 50000
#define EMAX 800000
#define BM 64

// Scratch (device globals — no allocation allowed)
__device__ float g_xw[(size_t)NMAX * D];   // x @ W
__device__ float g_p1[NMAX];               // x . w_pred[:128]
__device__ float g_p2[NMAX];               // x . w_pred[128:]
__device__ float g_deg[NMAX];              // weighted in-degree (init 1 self loop)
__device__ float g_dis[NMAX];              // deg^{-1/2}
__device__ int   g_cnt[NMAX];              // out-degree (by src)
__device__ int   g_rowstart[NMAX + 1];     // CSR row offsets (by src)
__device__ int   g_cursor[NMAX];           // fill cursors
__device__ int2  g_pack[EMAX];             // (tgt, ew bits) grouped by src
__device__ int   g_bsum[256];              // block sums for scan
__device__ int   g_boff[256];              // block offsets for scan

// ---------------------------------------------------------------------------
// K1: per-node dot products with the two halves of w_pred; init deg/cnt.
// ---------------------------------------------------------------------------
__global__ void k_precompute(const float* __restrict__ x,
                             const float* __restrict__ wp, int n) {
    int warp = (blockIdx.x * blockDim.x + threadIdx.x) >> 5;
    int lane = threadIdx.x & 31;
    if (warp >= n) return;
    float4 xv = ((const float4*)(x + (size_t)warp * D))[lane];
    float4 w1 = ((const float4*)wp)[lane];
    float4 w2 = ((const float4*)(wp + D))[lane];
    float s1 = xv.x * w1.x + xv.y * w1.y + xv.z * w1.z + xv.w * w1.w;
    float s2 = xv.x * w2.x + xv.y * w2.y + xv.z * w2.z + xv.w * w2.w;
#pragma unroll
    for (int o = 16; o > 0; o >>= 1) {
        s1 += __shfl_xor_sync(0xffffffffu, s1, o);
        s2 += __shfl_xor_sync(0xffffffffu, s2, o);
    }
    if (lane == 0) {
        g_p1[warp] = s1;
        g_p2[warp] = s2;
        g_deg[warp] = 1.0f;
        g_cnt[warp] = 0;
    }
}

// ---------------------------------------------------------------------------
// K2: out-degree counts by src.
// ---------------------------------------------------------------------------
__global__ void k_cnt(const int* __restrict__ src, int e) {
    int i = blockIdx.x * blockDim.x + threadIdx.x;
    if (i >= e) return;
    atomicAdd(&g_cnt[src[i]], 1);
}

// ---------------------------------------------------------------------------
// K3a/b/c: coalesced 3-phase exclusive scan of g_cnt -> rowstart/cursor.
// ---------------------------------------------------------------------------
__global__ void k_scan1(int n) {
    __shared__ int sd[256];
    int tid = threadIdx.x;
    int i = blockIdx.x * 256 + tid;
    int v = (i < n) ? g_cnt[i] : 0;
    sd[tid] = v;
    __syncthreads();
#pragma unroll
    for (int off = 1; off < 256; off <<= 1) {
        int u = (tid >= off) ? sd[tid - off] : 0;
        __syncthreads();
        sd[tid] += u;
        __syncthreads();
    }
    if (i < n) g_rowstart[i] = sd[tid] - v;  // block-local exclusive prefix
    if (tid == 255) g_bsum[blockIdx.x] = sd[255];
}

__global__ void k_scan2(int nb) {
    __shared__ int sd[256];
    int tid = threadIdx.x;
    int v = (tid < nb) ? g_bsum[tid] : 0;
    sd[tid] = v;
    __syncthreads();
#pragma unroll
    for (int off = 1; off < 256; off <<= 1) {
        int u = (tid >= off) ? sd[tid - off] : 0;
        __syncthreads();
        sd[tid] += u;
        __syncthreads();
    }
    g_boff[tid] = sd[tid] - v;
}

__global__ void k_scan3(int n, int e) {
    int i = blockIdx.x * 256 + threadIdx.x;
    if (i < n) {
        int r = g_rowstart[i] + g_boff[blockIdx.x];
        g_rowstart[i] = r;
        g_cursor[i] = r;
    }
    if (i == 0) g_rowstart[n] = e;
}

// ---------------------------------------------------------------------------
// K4: edge weights (sigmoid) + weighted in-degree + CSR fill by src
// (packed (tgt, ew) record; no separate g_ew array or fill pass).
// ---------------------------------------------------------------------------
__global__ void k_edgefill(const int* __restrict__ src,
                           const int* __restrict__ tgt,
                           const float* __restrict__ bp, int e) {
    int i = blockIdx.x * blockDim.x + threadIdx.x;
    if (i >= e) return;
    int s = src[i], t = tgt[i];
    float z = g_p1[s] + g_p2[t] + bp[0];
    float w = __fdividef(1.0f, 1.0f + __expf(-z));
    atomicAdd(&g_deg[t], w);
    int pos = atomicAdd(&g_cursor[s], 1);
    g_pack[pos] = make_int2(t, __float_as_int(w));
}

// ---------------------------------------------------------------------------
// K5: xw = x @ W with packed FFMA2 (proven R4 kernel, unchanged).
// ---------------------------------------------------------------------------
__global__ void k_gemm(const float* __restrict__ x, const float* __restrict__ W,
                       int n) {
    extern __shared__ float sh[];
    float* Ws = sh;            // [k][j]  128*128
    float* Xs = sh + D * D;    // [r][k]  BM*128
    int tid = threadIdx.x;
    int row0 = blockIdx.x * BM;

    for (int i = tid; i < D * D / 4; i += 256)
        ((float4*)Ws)[i] = ((const float4*)W)[i];
    for (int i = tid; i < BM * D / 4; i += 256) {
        int r = i >> 5;
        int gr = row0 + r;
        float4 v = make_float4(0.f, 0.f, 0.f, 0.f);
        if (gr < n) v = ((const float4*)x)[(size_t)gr * 32 + (i & 31)];
        ((float4*)Xs)[i] = v;
    }
    __syncthreads();

    int tcol = tid & 31;
    int trow = tid >> 5;

    unsigned long long acc[8][2];
#pragma unroll
    for (int i = 0; i < 8; i++) {
        acc[i][0] = 0ull;
        acc[i][1] = 0ull;
    }

#pragma unroll 4
    for (int k = 0; k < D; k++) {
        float4 bv = *((const float4*)&Ws[k * D + tcol * 4]);
        unsigned long long b01, b23;
        asm("mov.b64 %0, {%1, %2};" : "=l"(b01) : "f"(bv.x), "f"(bv.y));
        asm("mov.b64 %0, {%1, %2};" : "=l"(b23) : "f"(bv.z), "f"(bv.w));
#pragma unroll
        for (int i = 0; i < 8; i++) {
            float a = Xs[(trow * 8 + i) * D + k];
            unsigned long long aa;
            asm("mov.b64 %0, {%1, %1};" : "=l"(aa) : "f"(a));
            asm("fma.rn.f32x2 %0, %1, %2, %0;" : "+l"(acc[i][0])
                : "l"(aa), "l"(b01));
            asm("fma.rn.f32x2 %0, %1, %2, %0;" : "+l"(acc[i][1])
                : "l"(aa), "l"(b23));
        }
    }

#pragma unroll
    for (int i = 0; i < 8; i++) {
        int gr = row0 + trow * 8 + i;
        if (gr < n) {
            float c0, c1, c2, c3;
            asm("mov.b64 {%0, %1}, %2;" : "=f"(c0), "=f"(c1) : "l"(acc[i][0]));
            asm("mov.b64 {%0, %1}, %2;" : "=f"(c2), "=f"(c3) : "l"(acc[i][1]));
            *((float4*)&g_xw[(size_t)gr * D + tcol * 4]) =
                make_float4(c0, c1, c2, c3);
        }
    }
}

// ---------------------------------------------------------------------------
// K6: dis = rsqrt(deg); out = b + dis^2 * xw (self loop + bias; initializes
// the poisoned output buffer). Must complete before K7 (needs all dis).
// ---------------------------------------------------------------------------
__global__ void k_selfinit(const float* __restrict__ b, float* __restrict__ out,
                           int n) {
    int i = blockIdx.x * blockDim.x + threadIdx.x;
    if (i >= n * 32) return;
    int node = i >> 5;
    int c4 = i & 31;
    float dg = g_deg[node];
    float ds = (dg > 0.f) ? rsqrtf(dg) : 0.f;
    float sc = ds * ds;
    float4 xv = ((const float4*)g_xw)[i];
    float4 bv = ((const float4*)b)[c4];
    ((float4*)out)[i] = make_float4(bv.x + sc * xv.x, bv.y + sc * xv.y,
                                    bv.z + sc * xv.z, bv.w + sc * xv.w);
    if (c4 == 0) g_dis[node] = ds;
}

// ---------------------------------------------------------------------------
// K7: by-src scatter. Warp per SOURCE node: read the xw row ONCE (sequential),
// scale by dis[s]; edge metadata (tgt, ew*dis[tgt]) loaded one-edge-per-lane
// (coalesced int2 + random 4B dis), then per edge: shuffle-broadcast + one
// red.global.add.v4.f32 per lane. L2 traffic ~470MB vs 820MB in R4.
// ---------------------------------------------------------------------------
__global__ void k_scatter2(float* __restrict__ out, int n) {
    int s = (blockIdx.x * blockDim.x + threadIdx.x) >> 5;
    int lane = threadIdx.x & 31;
    if (s >= n) return;
    int p0 = g_rowstart[s];
    int cnt = g_rowstart[s + 1] - p0;
    if (cnt == 0) return;

    float ds = g_dis[s];
    float4 row = ((const float4*)g_xw)[(size_t)s * 32 + lane];
    row.x *= ds; row.y *= ds; row.z *= ds; row.w *= ds;

    for (int base = 0; base < cnt; base += 32) {
        int idx = base + lane;
        int t = 0;
        float c = 0.f;
        if (idx < cnt) {
            int2 pk = g_pack[p0 + idx];
            t = pk.x;
            c = __int_as_float(pk.y) * g_dis[t];
        }
        int m = min(32, cnt - base);
        for (int j = 0; j < m; j++) {
            int tj = __shfl_sync(0xffffffffu, t, j);
            float cj = __shfl_sync(0xffffffffu, c, j);
            float* o = out + (size_t)tj * D + lane * 4;
            asm volatile("red.global.add.v4.f32 [%0], {%1, %2, %3, %4};"
                         :: "l"(o), "f"(cj * row.x), "f"(cj * row.y),
                            "f"(cj * row.z), "f"(cj * row.w)
                         : "memory");
        }
    }
}

// ---------------------------------------------------------------------------
extern "C" void kernel_launch(void* const* d_in, const int* in_sizes, int n_in,
                              void* d_out, int out_size) {
    const float* x  = (const float*)d_in[0];
    const int*   ei = (const int*)d_in[1];
    const float* W  = (const float*)d_in[2];
    const float* b  = (const float*)d_in[3];
    const float* wp = (const float*)d_in[4];
    const float* bp = (const float*)d_in[5];
    float* out = (float*)d_out;

    int n = in_sizes[0] / D;
    int e = in_sizes[1] / 2;
    const int* src = ei;
    const int* tgt = ei + e;
    int nb = (n + 255) / 256;  // <= 256 blocks for n <= 65536

    int smem = (D * D + BM * D) * (int)sizeof(float);  // 96 KB
    cudaFuncSetAttribute(k_gemm, cudaFuncAttributeMaxDynamicSharedMemorySize, smem);

    k_precompute<<<(n + 7) / 8, 256>>>(x, wp, n);
    k_cnt<<<(e + 255) / 256, 256>>>(src, e);
    k_scan1<<<nb, 256>>>(n);
    k_scan2<<<1, 256>>>(nb);
    k_scan3<<<nb, 256>>>(n, e);
    k_edgefill<<<(e + 255) / 256, 256>>>(src, tgt, bp, e);
    k_gemm<<<(n + BM - 1) / BM, 256, smem>>>(x, W, n);
    k_selfinit<<<(n * 32 + 255) / 256, 256>>>(b, out, n);
    k_scatter2<<<(n * 32 + 255) / 256, 256>>>(out, n);
}

// round 7
// speedup vs baseline: 1.9874x; 1.3490x over previous
#include <cuda_runtime.h>
#include <math.h>

#define D 128
#define NMAX 50000
#define EMAX 800000
#define BM 64

// Scratch (device globals — no allocation allowed)
__device__ float g_xw[(size_t)NMAX * D];   // x @ W
__device__ float g_p1[NMAX];               // x . w_pred[:128]
__device__ float g_p2[NMAX];               // x . w_pred[128:]
__device__ float g_deg[NMAX];              // weighted in-degree (init 1 self loop)
__device__ float g_dis[NMAX];              // deg^{-1/2}
__device__ int   g_cnt[NMAX];              // in-degree count (by tgt)
__device__ int   g_rowstart[NMAX + 1];     // CSR row offsets (by tgt)
__device__ int   g_cursor[NMAX];           // fill cursors
__device__ int2  g_pack[EMAX];             // (src, ew bits) grouped by tgt
__device__ int   g_bsum[256];              // block sums for scan
__device__ int   g_boff[256];              // block offsets for scan

// ---------------------------------------------------------------------------
// K1: per-node dot products with the two halves of w_pred; init deg/cnt.
// ---------------------------------------------------------------------------
__global__ void k_precompute(const float* __restrict__ x,
                             const float* __restrict__ wp, int n) {
    int warp = (blockIdx.x * blockDim.x + threadIdx.x) >> 5;
    int lane = threadIdx.x & 31;
    if (warp >= n) return;
    float4 xv = ((const float4*)(x + (size_t)warp * D))[lane];
    float4 w1 = ((const float4*)wp)[lane];
    float4 w2 = ((const float4*)(wp + D))[lane];
    float s1 = xv.x * w1.x + xv.y * w1.y + xv.z * w1.z + xv.w * w1.w;
    float s2 = xv.x * w2.x + xv.y * w2.y + xv.z * w2.z + xv.w * w2.w;
#pragma unroll
    for (int o = 16; o > 0; o >>= 1) {
        s1 += __shfl_xor_sync(0xffffffffu, s1, o);
        s2 += __shfl_xor_sync(0xffffffffu, s2, o);
    }
    if (lane == 0) {
        g_p1[warp] = s1;
        g_p2[warp] = s2;
        g_deg[warp] = 1.0f;
        g_cnt[warp] = 0;
    }
}

// ---------------------------------------------------------------------------
// K2: in-degree counts by target.
// ---------------------------------------------------------------------------
__global__ void k_cnt(const int* __restrict__ tgt, int e) {
    int i = blockIdx.x * blockDim.x + threadIdx.x;
    if (i >= e) return;
    atomicAdd(&g_cnt[tgt[i]], 1);
}

// ---------------------------------------------------------------------------
// K3a/b/c: coalesced 3-phase exclusive scan of g_cnt -> rowstart/cursor.
// ---------------------------------------------------------------------------
__global__ void k_scan1(int n) {
    __shared__ int sd[256];
    int tid = threadIdx.x;
    int i = blockIdx.x * 256 + tid;
    int v = (i < n) ? g_cnt[i] : 0;
    sd[tid] = v;
    __syncthreads();
#pragma unroll
    for (int off = 1; off < 256; off <<= 1) {
        int u = (tid >= off) ? sd[tid - off] : 0;
        __syncthreads();
        sd[tid] += u;
        __syncthreads();
    }
    if (i < n) g_rowstart[i] = sd[tid] - v;
    if (tid == 255) g_bsum[blockIdx.x] = sd[255];
}

__global__ void k_scan2(int nb) {
    __shared__ int sd[256];
    int tid = threadIdx.x;
    int v = (tid < nb) ? g_bsum[tid] : 0;
    sd[tid] = v;
    __syncthreads();
#pragma unroll
    for (int off = 1; off < 256; off <<= 1) {
        int u = (tid >= off) ? sd[tid - off] : 0;
        __syncthreads();
        sd[tid] += u;
        __syncthreads();
    }
    g_boff[tid] = sd[tid] - v;
}

__global__ void k_scan3(int n, int e) {
    int i = blockIdx.x * 256 + threadIdx.x;
    if (i < n) {
        int r = g_rowstart[i] + g_boff[blockIdx.x];
        g_rowstart[i] = r;
        g_cursor[i] = r;
    }
    if (i == 0) g_rowstart[n] = e;
}

// ---------------------------------------------------------------------------
// K4: edge weights (sigmoid) + weighted in-degree + CSR fill by TARGET
// (packed (src, ew) record).
// ---------------------------------------------------------------------------
__global__ void k_edgefill(const int* __restrict__ src,
                           const int* __restrict__ tgt,
                           const float* __restrict__ bp, int e) {
    int i = blockIdx.x * blockDim.x + threadIdx.x;
    if (i >= e) return;
    int s = src[i], t = tgt[i];
    float z = g_p1[s] + g_p2[t] + bp[0];
    float w = __fdividef(1.0f, 1.0f + __expf(-z));
    atomicAdd(&g_deg[t], w);
    int pos = atomicAdd(&g_cursor[t], 1);
    g_pack[pos] = make_int2(s, __float_as_int(w));
}

// ---------------------------------------------------------------------------
// K5: dis = rsqrt(deg). Tiny; must run after edgefill, before aggregate.
// ---------------------------------------------------------------------------
__global__ void k_dis(int n) {
    int i = blockIdx.x * blockDim.x + threadIdx.x;
    if (i >= n) return;
    float dg = g_deg[i];
    g_dis[i] = (dg > 0.f) ? rsqrtf(dg) : 0.f;
}

// ---------------------------------------------------------------------------
// K6: xw = x @ W with packed FFMA2 (proven R4 kernel, unchanged).
// ---------------------------------------------------------------------------
__global__ void k_gemm(const float* __restrict__ x, const float* __restrict__ W,
                       int n) {
    extern __shared__ float sh[];
    float* Ws = sh;            // [k][j]  128*128
    float* Xs = sh + D * D;    // [r][k]  BM*128
    int tid = threadIdx.x;
    int row0 = blockIdx.x * BM;

    for (int i = tid; i < D * D / 4; i += 256)
        ((float4*)Ws)[i] = ((const float4*)W)[i];
    for (int i = tid; i < BM * D / 4; i += 256) {
        int r = i >> 5;
        int gr = row0 + r;
        float4 v = make_float4(0.f, 0.f, 0.f, 0.f);
        if (gr < n) v = ((const float4*)x)[(size_t)gr * 32 + (i & 31)];
        ((float4*)Xs)[i] = v;
    }
    __syncthreads();

    int tcol = tid & 31;
    int trow = tid >> 5;

    unsigned long long acc[8][2];
#pragma unroll
    for (int i = 0; i < 8; i++) {
        acc[i][0] = 0ull;
        acc[i][1] = 0ull;
    }

#pragma unroll 4
    for (int k = 0; k < D; k++) {
        float4 bv = *((const float4*)&Ws[k * D + tcol * 4]);
        unsigned long long b01, b23;
        asm("mov.b64 %0, {%1, %2};" : "=l"(b01) : "f"(bv.x), "f"(bv.y));
        asm("mov.b64 %0, {%1, %2};" : "=l"(b23) : "f"(bv.z), "f"(bv.w));
#pragma unroll
        for (int i = 0; i < 8; i++) {
            float a = Xs[(trow * 8 + i) * D + k];
            unsigned long long aa;
            asm("mov.b64 %0, {%1, %1};" : "=l"(aa) : "f"(a));
            asm("fma.rn.f32x2 %0, %1, %2, %0;" : "+l"(acc[i][0])
                : "l"(aa), "l"(b01));
            asm("fma.rn.f32x2 %0, %1, %2, %0;" : "+l"(acc[i][1])
                : "l"(aa), "l"(b23));
        }
    }

#pragma unroll
    for (int i = 0; i < 8; i++) {
        int gr = row0 + trow * 8 + i;
        if (gr < n) {
            float c0, c1, c2, c3;
            asm("mov.b64 {%0, %1}, %2;" : "=f"(c0), "=f"(c1) : "l"(acc[i][0]));
            asm("mov.b64 {%0, %1}, %2;" : "=f"(c2), "=f"(c3) : "l"(acc[i][1]));
            *((float4*)&g_xw[(size_t)gr * D + tcol * 4]) =
                make_float4(c0, c1, c2, c3);
        }
    }
}

// ---------------------------------------------------------------------------
// K7: atomic-free aggregation, warp per TARGET node. Lane-parallel edge
// metadata (coalesced int2 pack + random 4B dis[src]); 4-way unrolled
// independent float4 gathers (L2-resident). Self term + bias folded in;
// each output row written exactly once. No atomics, no RED traffic.
// ---------------------------------------------------------------------------
__global__ void k_aggregate(const float* __restrict__ b,
                            float* __restrict__ out, int n) {
    int t = (blockIdx.x * blockDim.x + threadIdx.x) >> 5;
    int lane = threadIdx.x & 31;
    if (t >= n) return;
    float dt = g_dis[t];
    float4 xv = ((const float4*)g_xw)[(size_t)t * 32 + lane];
    float sc = dt * dt;
    float4 acc = make_float4(sc * xv.x, sc * xv.y, sc * xv.z, sc * xv.w);

    int p0 = g_rowstart[t];
    int cnt = g_rowstart[t + 1] - p0;

    for (int base = 0; base < cnt; base += 32) {
        int idx = base + lane;
        int s = 0;
        float c = 0.f;
        if (idx < cnt) {
            int2 pk = g_pack[p0 + idx];
            s = pk.x;
            c = __int_as_float(pk.y) * g_dis[s] * dt;
        }
        int m = min(32, cnt - base);
        int j = 0;
        for (; j + 4 <= m; j += 4) {
            int s0 = __shfl_sync(0xffffffffu, s, j);
            int s1 = __shfl_sync(0xffffffffu, s, j + 1);
            int s2 = __shfl_sync(0xffffffffu, s, j + 2);
            int s3 = __shfl_sync(0xffffffffu, s, j + 3);
            float c0 = __shfl_sync(0xffffffffu, c, j);
            float c1 = __shfl_sync(0xffffffffu, c, j + 1);
            float c2 = __shfl_sync(0xffffffffu, c, j + 2);
            float c3 = __shfl_sync(0xffffffffu, c, j + 3);
            float4 v0 = ((const float4*)g_xw)[(size_t)s0 * 32 + lane];
            float4 v1 = ((const float4*)g_xw)[(size_t)s1 * 32 + lane];
            float4 v2 = ((const float4*)g_xw)[(size_t)s2 * 32 + lane];
            float4 v3 = ((const float4*)g_xw)[(size_t)s3 * 32 + lane];
            acc.x += c0 * v0.x + c1 * v1.x + c2 * v2.x + c3 * v3.x;
            acc.y += c0 * v0.y + c1 * v1.y + c2 * v2.y + c3 * v3.y;
            acc.z += c0 * v0.z + c1 * v1.z + c2 * v2.z + c3 * v3.z;
            acc.w += c0 * v0.w + c1 * v1.w + c2 * v2.w + c3 * v3.w;
        }
        for (; j < m; j++) {
            int sj = __shfl_sync(0xffffffffu, s, j);
            float cj = __shfl_sync(0xffffffffu, c, j);
            float4 v = ((const float4*)g_xw)[(size_t)sj * 32 + lane];
            acc.x += cj * v.x;
            acc.y += cj * v.y;
            acc.z += cj * v.z;
            acc.w += cj * v.w;
        }
    }

    float4 bv = ((const float4*)b)[lane];
    ((float4*)out)[(size_t)t * 32 + lane] =
        make_float4(acc.x + bv.x, acc.y + bv.y, acc.z + bv.z, acc.w + bv.w);
}

// ---------------------------------------------------------------------------
extern "C" void kernel_launch(void* const* d_in, const int* in_sizes, int n_in,
                              void* d_out, int out_size) {
    const float* x  = (const float*)d_in[0];
    const int*   ei = (const int*)d_in[1];
    const float* W  = (const float*)d_in[2];
    const float* b  = (const float*)d_in[3];
    const float* wp = (const float*)d_in[4];
    const float* bp = (const float*)d_in[5];
    float* out = (float*)d_out;

    int n = in_sizes[0] / D;
    int e = in_sizes[1] / 2;
    const int* src = ei;
    const int* tgt = ei + e;
    int nb = (n + 255) / 256;  // <= 256 blocks for n <= 65536

    int smem = (D * D + BM * D) * (int)sizeof(float);  // 96 KB
    cudaFuncSetAttribute(k_gemm, cudaFuncAttributeMaxDynamicSharedMemorySize, smem);

    k_precompute<<<(n + 7) / 8, 256>>>(x, wp, n);
    k_cnt<<<(e + 255) / 256, 256>>>(tgt, e);
    k_scan1<<<nb, 256>>>(n);
    k_scan2<<<1, 256>>>(nb);
    k_scan3<<<nb, 256>>>(n, e);
    k_edgefill<<<(e + 255) / 256, 256>>>(src, tgt, bp, e);
    k_dis<<<(n + 255) / 256, 256>>>(n);
    k_gemm<<<(n + BM - 1) / BM, 256, smem>>>(x, W, n);
    k_aggregate<<<(n * 32 + 255) / 256, 256>>>(b, out, n);
}

// round 8
// speedup vs baseline: 2.1911x; 1.1025x over previous
#include <cuda_runtime.h>
#include <cuda_fp16.h>
#include <math.h>

#define D 128
#define NMAX 50000
#define EMAX 800000
#define BM 64

// Scratch (device globals — zero-initialized at load; k_reset keeps them zero)
__device__ float g_xw[(size_t)NMAX * D];    // x @ W (fp32, self term)
__device__ uint2 g_xwh[(size_t)NMAX * 32];  // x @ W packed 4x fp16 per lane
__device__ float g_p1[NMAX];                // x . w_pred[:128]
__device__ float g_p2[NMAX];                // x . w_pred[128:]
__device__ float g_degex[NMAX];             // weighted in-degree EXCESS (deg-1)
__device__ int   g_cnt[NMAX];               // in-degree count (by tgt)
__device__ int   g_rowstart[NMAX + 1];      // CSR row offsets (by tgt)
__device__ int   g_cursor[NMAX];            // fill cursors
__device__ int2  g_pack[EMAX];              // (src, ew bits) grouped by tgt
__device__ int   g_bsum[256];               // block sums for scan
__device__ int   g_boff[256];               // block offsets for scan

// ---------------------------------------------------------------------------
// K1 (fused): blocks [0, npre): per-node dots with w_pred halves.
//             blocks [npre, ...): in-degree counts by target (g_cnt starts 0).
// ---------------------------------------------------------------------------
__global__ void k_precnt(const float* __restrict__ x,
                         const float* __restrict__ wp,
                         const int* __restrict__ tgt, int n, int e, int npre) {
    if ((int)blockIdx.x < npre) {
        int warp = (blockIdx.x * 256 + threadIdx.x) >> 5;
        int lane = threadIdx.x & 31;
        if (warp >= n) return;
        float4 xv = ((const float4*)(x + (size_t)warp * D))[lane];
        float4 w1 = ((const float4*)wp)[lane];
        float4 w2 = ((const float4*)(wp + D))[lane];
        float s1 = xv.x * w1.x + xv.y * w1.y + xv.z * w1.z + xv.w * w1.w;
        float s2 = xv.x * w2.x + xv.y * w2.y + xv.z * w2.z + xv.w * w2.w;
#pragma unroll
        for (int o = 16; o > 0; o >>= 1) {
            s1 += __shfl_xor_sync(0xffffffffu, s1, o);
            s2 += __shfl_xor_sync(0xffffffffu, s2, o);
        }
        if (lane == 0) {
            g_p1[warp] = s1;
            g_p2[warp] = s2;
        }
    } else {
        int i = (blockIdx.x - npre) * 256 + threadIdx.x;
        if (i >= e) return;
        atomicAdd(&g_cnt[tgt[i]], 1);
    }
}

// ---------------------------------------------------------------------------
// K2a/b/c: coalesced 3-phase exclusive scan of g_cnt -> rowstart/cursor.
// ---------------------------------------------------------------------------
__global__ void k_scan1(int n) {
    __shared__ int sd[256];
    int tid = threadIdx.x;
    int i = blockIdx.x * 256 + tid;
    int v = (i < n) ? g_cnt[i] : 0;
    sd[tid] = v;
    __syncthreads();
#pragma unroll
    for (int off = 1; off < 256; off <<= 1) {
        int u = (tid >= off) ? sd[tid - off] : 0;
        __syncthreads();
        sd[tid] += u;
        __syncthreads();
    }
    if (i < n) g_rowstart[i] = sd[tid] - v;
    if (tid == 255) g_bsum[blockIdx.x] = sd[255];
}

__global__ void k_scan2(int nb) {
    __shared__ int sd[256];
    int tid = threadIdx.x;
    int v = (tid < nb) ? g_bsum[tid] : 0;
    sd[tid] = v;
    __syncthreads();
#pragma unroll
    for (int off = 1; off < 256; off <<= 1) {
        int u = (tid >= off) ? sd[tid - off] : 0;
        __syncthreads();
        sd[tid] += u;
        __syncthreads();
    }
    g_boff[tid] = sd[tid] - v;
}

__global__ void k_scan3(int n, int e) {
    int i = blockIdx.x * 256 + threadIdx.x;
    if (i < n) {
        int r = g_rowstart[i] + g_boff[blockIdx.x];
        g_rowstart[i] = r;
        g_cursor[i] = r;
    }
    if (i == 0) g_rowstart[n] = e;
}

// ---------------------------------------------------------------------------
// K3 (fused): blocks [0, ngemm): FFMA2 GEMM (writes fp32 g_xw + fp16 g_xwh).
//             blocks [ngemm, ...): edge sigmoid + degex atomics + CSR fill.
// Independent work, disjoint outputs; mixes FMA-heavy with atomic/L2-heavy.
// ---------------------------------------------------------------------------
__global__ void k_gemmedge(const float* __restrict__ x,
                           const float* __restrict__ W,
                           const int* __restrict__ src,
                           const int* __restrict__ tgt,
                           const float* __restrict__ bp,
                           int n, int e, int ngemm) {
    if ((int)blockIdx.x >= ngemm) {
        int i = (blockIdx.x - ngemm) * 256 + threadIdx.x;
        if (i >= e) return;
        int s = src[i], t = tgt[i];
        float z = g_p1[s] + g_p2[t] + bp[0];
        float w = __fdividef(1.0f, 1.0f + __expf(-z));
        atomicAdd(&g_degex[t], w);
        int pos = atomicAdd(&g_cursor[t], 1);
        g_pack[pos] = make_int2(s, __float_as_int(w));
        return;
    }

    extern __shared__ float sh[];
    float* Ws = sh;            // [k][j]  128*128
    float* Xs = sh + D * D;    // [r][k]  BM*128
    int tid = threadIdx.x;
    int row0 = blockIdx.x * BM;

    for (int i = tid; i < D * D / 4; i += 256)
        ((float4*)Ws)[i] = ((const float4*)W)[i];
    for (int i = tid; i < BM * D / 4; i += 256) {
        int r = i >> 5;
        int gr = row0 + r;
        float4 v = make_float4(0.f, 0.f, 0.f, 0.f);
        if (gr < n) v = ((const float4*)x)[(size_t)gr * 32 + (i & 31)];
        ((float4*)Xs)[i] = v;
    }
    __syncthreads();

    int tcol = tid & 31;
    int trow = tid >> 5;

    unsigned long long acc[8][2];
#pragma unroll
    for (int i = 0; i < 8; i++) {
        acc[i][0] = 0ull;
        acc[i][1] = 0ull;
    }

#pragma unroll 4
    for (int k = 0; k < D; k++) {
        float4 bv = *((const float4*)&Ws[k * D + tcol * 4]);
        unsigned long long b01, b23;
        asm("mov.b64 %0, {%1, %2};" : "=l"(b01) : "f"(bv.x), "f"(bv.y));
        asm("mov.b64 %0, {%1, %2};" : "=l"(b23) : "f"(bv.z), "f"(bv.w));
#pragma unroll
        for (int i = 0; i < 8; i++) {
            float a = Xs[(trow * 8 + i) * D + k];
            unsigned long long aa;
            asm("mov.b64 %0, {%1, %1};" : "=l"(aa) : "f"(a));
            asm("fma.rn.f32x2 %0, %1, %2, %0;" : "+l"(acc[i][0])
                : "l"(aa), "l"(b01));
            asm("fma.rn.f32x2 %0, %1, %2, %0;" : "+l"(acc[i][1])
                : "l"(aa), "l"(b23));
        }
    }

#pragma unroll
    for (int i = 0; i < 8; i++) {
        int gr = row0 + trow * 8 + i;
        if (gr < n) {
            float c0, c1, c2, c3;
            asm("mov.b64 {%0, %1}, %2;" : "=f"(c0), "=f"(c1) : "l"(acc[i][0]));
            asm("mov.b64 {%0, %1}, %2;" : "=f"(c2), "=f"(c3) : "l"(acc[i][1]));
            *((float4*)&g_xw[(size_t)gr * D + tcol * 4]) =
                make_float4(c0, c1, c2, c3);
            __half2 h01 = __floats2half2_rn(c0, c1);
            __half2 h23 = __floats2half2_rn(c2, c3);
            uint2 pk;
            pk.x = *(unsigned*)&h01;
            pk.y = *(unsigned*)&h23;
            g_xwh[(size_t)gr * 32 + tcol] = pk;
        }
    }
}

// ---------------------------------------------------------------------------
// K4: atomic-free aggregation, warp per TARGET node. Lane-parallel edge
// metadata (+ on-the-fly rsqrt of 1+degex); 4-way unrolled fp16 row gathers
// (256B/edge instead of 512B). Self term fp32, bias folded; row written once.
// ---------------------------------------------------------------------------
__global__ void k_aggregate(const float* __restrict__ b,
                            float* __restrict__ out, int n) {
    int t = (blockIdx.x * blockDim.x + threadIdx.x) >> 5;
    int lane = threadIdx.x & 31;
    if (t >= n) return;
    float dt = rsqrtf(1.0f + g_degex[t]);
    float4 xv = ((const float4*)g_xw)[(size_t)t * 32 + lane];
    float sc = dt * dt;
    float4 acc = make_float4(sc * xv.x, sc * xv.y, sc * xv.z, sc * xv.w);

    int p0 = g_rowstart[t];
    int cnt = g_rowstart[t + 1] - p0;

    for (int base = 0; base < cnt; base += 32) {
        int idx = base + lane;
        int s = 0;
        float c = 0.f;
        if (idx < cnt) {
            int2 pk = g_pack[p0 + idx];
            s = pk.x;
            c = __int_as_float(pk.y) * rsqrtf(1.0f + g_degex[s]) * dt;
        }
        int m = min(32, cnt - base);
        int j = 0;
        for (; j + 4 <= m; j += 4) {
            int s0 = __shfl_sync(0xffffffffu, s, j);
            int s1 = __shfl_sync(0xffffffffu, s, j + 1);
            int s2 = __shfl_sync(0xffffffffu, s, j + 2);
            int s3 = __shfl_sync(0xffffffffu, s, j + 3);
            float c0 = __shfl_sync(0xffffffffu, c, j);
            float c1 = __shfl_sync(0xffffffffu, c, j + 1);
            float c2 = __shfl_sync(0xffffffffu, c, j + 2);
            float c3 = __shfl_sync(0xffffffffu, c, j + 3);
            uint2 v0 = g_xwh[(size_t)s0 * 32 + lane];
            uint2 v1 = g_xwh[(size_t)s1 * 32 + lane];
            uint2 v2 = g_xwh[(size_t)s2 * 32 + lane];
            uint2 v3 = g_xwh[(size_t)s3 * 32 + lane];
            float2 a0 = __half22float2(*(__half2*)&v0.x);
            float2 b0 = __half22float2(*(__half2*)&v0.y);
            float2 a1 = __half22float2(*(__half2*)&v1.x);
            float2 b1 = __half22float2(*(__half2*)&v1.y);
            float2 a2 = __half22float2(*(__half2*)&v2.x);
            float2 b2 = __half22float2(*(__half2*)&v2.y);
            float2 a3 = __half22float2(*(__half2*)&v3.x);
            float2 b3 = __half22float2(*(__half2*)&v3.y);
            acc.x += c0 * a0.x + c1 * a1.x + c2 * a2.x + c3 * a3.x;
            acc.y += c0 * a0.y + c1 * a1.y + c2 * a2.y + c3 * a3.y;
            acc.z += c0 * b0.x + c1 * b1.x + c2 * b2.x + c3 * b3.x;
            acc.w += c0 * b0.y + c1 * b1.y + c2 * b2.y + c3 * b3.y;
        }
        for (; j < m; j++) {
            int sj = __shfl_sync(0xffffffffu, s, j);
            float cj = __shfl_sync(0xffffffffu, c, j);
            uint2 v = g_xwh[(size_t)sj * 32 + lane];
            float2 a = __half22float2(*(__half2*)&v.x);
            float2 d = __half22float2(*(__half2*)&v.y);
            acc.x += cj * a.x;
            acc.y += cj * a.y;
            acc.z += cj * d.x;
            acc.w += cj * d.y;
        }
    }

    float4 bv = ((const float4*)b)[lane];
    ((float4*)out)[(size_t)t * 32 + lane] =
        make_float4(acc.x + bv.x, acc.y + bv.y, acc.z + bv.z, acc.w + bv.w);
}

// ---------------------------------------------------------------------------
// K5: restore g_cnt/g_degex to zero so every invocation starts identically.
// ---------------------------------------------------------------------------
__global__ void k_reset(int n) {
    int i = blockIdx.x * blockDim.x + threadIdx.x;
    if (i >= n) return;
    g_cnt[i] = 0;
    g_degex[i] = 0.0f;
}

// ---------------------------------------------------------------------------
extern "C" void kernel_launch(void* const* d_in, const int* in_sizes, int n_in,
                              void* d_out, int out_size) {
    const float* x  = (const float*)d_in[0];
    const int*   ei = (const int*)d_in[1];
    const float* W  = (const float*)d_in[2];
    const float* b  = (const float*)d_in[3];
    const float* wp = (const float*)d_in[4];
    const float* bp = (const float*)d_in[5];
    float* out = (float*)d_out;

    int n = in_sizes[0] / D;
    int e = in_sizes[1] / 2;
    const int* src = ei;
    const int* tgt = ei + e;
    int nb = (n + 255) / 256;        // scan blocks (<=256)
    int npre = (n + 7) / 8;          // precompute blocks (8 warps each)
    int ncntb = (e + 255) / 256;     // cnt / edgefill blocks
    int ngemm = (n + BM - 1) / BM;   // gemm blocks

    int smem = (D * D + BM * D) * (int)sizeof(float);  // 96 KB
    cudaFuncSetAttribute(k_gemmedge, cudaFuncAttributeMaxDynamicSharedMemorySize,
                         smem);

    k_precnt<<<npre + ncntb, 256>>>(x, wp, tgt, n, e, npre);
    k_scan1<<<nb, 256>>>(n);
    k_scan2<<<1, 256>>>(nb);
    k_scan3<<<nb, 256>>>(n, e);
    k_gemmedge<<<ngemm + ncntb, 256, smem>>>(x, W, src, tgt, bp, n, e, ngemm);
    k_aggregate<<<(n * 32 + 255) / 256, 256>>>(b, out, n);
    k_reset<<<nb, 256>>>(n);
}